// round 2
// baseline (speedup 1.0000x reference)
#include <cuda_runtime.h>

#define NN 16384
#define D 64
#define TITER 4
#define SPAD 32        // pad column-sum accumulators across L2 slices
#define RSTRIDE 66     // sU row stride (floats): bank-conflict-free a-loads
#define TILE_ROWS 64

// Scratch (allocation-free rule: __device__ globals)
__device__ float g_pos[NN];
__device__ float g_neg[NN];
__device__ float g_ab[2 * D];                       // a = W3*relu(w4), b = W3*relu(-w4)
__device__ __align__(16) float g_u[2][NN * D];      // ping-pong u buffers
__device__ float g_sums[TITER][D * SPAD];           // s1..s4 column sums (padded)

// ---------------------------------------------------------------------------
// k_pre: zero atomic accumulators (inside the graph, every replay) and
// precompute a,b. 1 block x 256 threads.
// ---------------------------------------------------------------------------
__global__ void k_pre(const float* __restrict__ W3, const float* __restrict__ w4) {
    int t = threadIdx.x;
    float* s = (float*)g_sums;
    for (int i = t; i < TITER * D * SPAD; i += blockDim.x) s[i] = 0.f;
    if (t < D) {
        float a = 0.f, b = 0.f;
#pragma unroll
        for (int k = 0; k < D; k++) {
            float w = w4[k];
            float W = W3[t * D + k];
            a = fmaf(W, fmaxf(w, 0.f), a);
            b = fmaf(W, fmaxf(-w, 0.f), b);
        }
        g_ab[t]     = a;
        g_ab[D + t] = b;
    }
}

// ---------------------------------------------------------------------------
// k_rowsum: pos[i] = sum_j relu(g[i][j]), neg[i] = sum_j relu(-g[i][j]).
// One block per row, float4 streaming loads. The 1.07 GB single pass.
// ---------------------------------------------------------------------------
__global__ void k_rowsum(const float* __restrict__ graph) {
    int row = blockIdx.x;
    const float4* g = reinterpret_cast<const float4*>(graph + (size_t)row * NN);
    float p = 0.f, n = 0.f;
#pragma unroll 4
    for (int i = threadIdx.x; i < NN / 4; i += 256) {
        float4 v = __ldcs(g + i);
        p += fmaxf(v.x, 0.f) + fmaxf(v.y, 0.f) + fmaxf(v.z, 0.f) + fmaxf(v.w, 0.f);
        n += fmaxf(-v.x, 0.f) + fmaxf(-v.y, 0.f) + fmaxf(-v.z, 0.f) + fmaxf(-v.w, 0.f);
    }
#pragma unroll
    for (int o = 16; o; o >>= 1) {
        p += __shfl_xor_sync(0xffffffffu, p, o);
        n += __shfl_xor_sync(0xffffffffu, n, o);
    }
    __shared__ float sp[8], sn[8];
    int lane = threadIdx.x & 31, w = threadIdx.x >> 5;
    if (lane == 0) { sp[w] = p; sn[w] = n; }
    __syncthreads();
    if (threadIdx.x == 0) {
        float P = 0.f, Q = 0.f;
#pragma unroll
        for (int i = 0; i < 8; i++) { P += sp[i]; Q += sn[i]; }
        g_pos[row] = P;
        g_neg[row] = Q;
    }
}

// ---------------------------------------------------------------------------
// k_first: u1 = relu(base), base = x*w1 + pos*a + neg*b. Elementwise + colsum.
// 256 blocks x 256 threads; block handles 64 rows.
// ---------------------------------------------------------------------------
__global__ __launch_bounds__(256) void k_first(const int* __restrict__ s_mask,
                                               const float* __restrict__ w1) {
    __shared__ float svec[3 * D];
    __shared__ float scol[D];
    int tid = threadIdx.x;
    if (tid < D) {
        svec[tid]         = w1[tid];
        svec[D + tid]     = g_ab[tid];
        svec[2 * D + tid] = g_ab[D + tid];
        scol[tid] = 0.f;
    }
    __syncthreads();

    int row0 = blockIdx.x * TILE_ROWS;
    float* u_out = g_u[0];
    int d  = (tid & 7) * 8;          // 8 consecutive cols
    int rg = tid >> 3;               // 32 row groups x 2 rows
    float colp[8];
#pragma unroll
    for (int j = 0; j < 8; j++) colp[j] = 0.f;

#pragma unroll
    for (int r = 0; r < 2; r++) {
        int row = row0 + rg * 2 + r;
        float xm = (float)s_mask[row];
        float P = g_pos[row], Qn = g_neg[row];
        float4 o0, o1;
        float v[8];
#pragma unroll
        for (int j = 0; j < 8; j++) {
            int dd = d + j;
            v[j] = fmaxf(xm * svec[dd] + P * svec[D + dd] + Qn * svec[2 * D + dd], 0.f);
            colp[j] += v[j];
        }
        o0 = make_float4(v[0], v[1], v[2], v[3]);
        o1 = make_float4(v[4], v[5], v[6], v[7]);
        float4* dst = (float4*)(u_out + (size_t)row * D + d);
        dst[0] = o0; dst[1] = o1;
    }
#pragma unroll
    for (int j = 0; j < 8; j++) atomicAdd(&scol[d + j], colp[j]);
    __syncthreads();
    if (tid < D) atomicAdd(&g_sums[0][tid * SPAD], scol[tid]);
}

// ---------------------------------------------------------------------------
// k_iter2: u_new = relu(base + c - u @ W2^T),  c = W2 @ s_prev.
// Register-blocked GEMM: 256 blocks x 256 threads, 64 rows/block,
// thread tile = 2 rows x 8 cols. One __syncthreads in the hot path.
// ---------------------------------------------------------------------------
__global__ __launch_bounds__(256) void k_iter2(int ib, int ob, int is, int os,
                                               const int* __restrict__ s_mask,
                                               const float* __restrict__ w1,
                                               const float* __restrict__ W2) {
    __shared__ float sU[TILE_ROWS * RSTRIDE];  // u tile, stride 66
    __shared__ float sW[D * D];                // W2^T: sW[k*64 + d]
    __shared__ float sC[D];                    // c = W2 @ s
    __shared__ float svec[3 * D];              // w1 | a | b
    __shared__ float scol[D];

    int tid = threadIdx.x;
    int row0 = blockIdx.x * TILE_ROWS;
    const float* __restrict__ u_in = g_u[ib];
    float* __restrict__ u_out = g_u[ob];

    // load u tile (coalesced float2 -> padded smem rows)
    {
        const float2* src = (const float2*)(u_in + (size_t)row0 * D);
#pragma unroll
        for (int t = 0; t < 8; t++) {            // 64*32 float2 / 256 = 8
            int p = tid + t * 256;
            int r = p >> 5, k2 = p & 31;
            float2 v = src[p];
            sU[r * RSTRIDE + k2 * 2]     = v.x;
            sU[r * RSTRIDE + k2 * 2 + 1] = v.y;
        }
    }
    // W2[d][k] -> sW[k*64 + d]  (transpose once)
#pragma unroll
    for (int t = 0; t < 16; t++) {
        int p = tid + t * 256;
        int d = p >> 6, k = p & 63;
        sW[k * D + d] = W2[p];
    }
    if (tid < D) {
        svec[tid]         = w1[tid];
        svec[D + tid]     = g_ab[tid];
        svec[2 * D + tid] = g_ab[D + tid];
        float acc = 0.f;
#pragma unroll
        for (int k = 0; k < D; k++)
            acc = fmaf(W2[tid * D + k], g_sums[is][k * SPAD], acc);
        sC[tid] = acc;
        scol[tid] = 0.f;
    }
    __syncthreads();

    const int cg = tid & 7;          // cols cg*8 .. cg*8+7
    const int rg = tid >> 3;         // rows rg*2, rg*2+1
    float acc[2][8];
#pragma unroll
    for (int r = 0; r < 2; r++)
#pragma unroll
        for (int j = 0; j < 8; j++) acc[r][j] = 0.f;

    const float* uB = &sU[rg * 2 * RSTRIDE];
    const float* wB = &sW[cg * 8];

#pragma unroll 8
    for (int k = 0; k < D; k++) {
        float4 b0 = *(const float4*)(wB + k * D);
        float4 b1 = *(const float4*)(wB + k * D + 4);
        float a0 = uB[k];
        float a1 = uB[RSTRIDE + k];
        acc[0][0] = fmaf(a0, b0.x, acc[0][0]);
        acc[0][1] = fmaf(a0, b0.y, acc[0][1]);
        acc[0][2] = fmaf(a0, b0.z, acc[0][2]);
        acc[0][3] = fmaf(a0, b0.w, acc[0][3]);
        acc[0][4] = fmaf(a0, b1.x, acc[0][4]);
        acc[0][5] = fmaf(a0, b1.y, acc[0][5]);
        acc[0][6] = fmaf(a0, b1.z, acc[0][6]);
        acc[0][7] = fmaf(a0, b1.w, acc[0][7]);
        acc[1][0] = fmaf(a1, b0.x, acc[1][0]);
        acc[1][1] = fmaf(a1, b0.y, acc[1][1]);
        acc[1][2] = fmaf(a1, b0.z, acc[1][2]);
        acc[1][3] = fmaf(a1, b0.w, acc[1][3]);
        acc[1][4] = fmaf(a1, b1.x, acc[1][4]);
        acc[1][5] = fmaf(a1, b1.y, acc[1][5]);
        acc[1][6] = fmaf(a1, b1.z, acc[1][6]);
        acc[1][7] = fmaf(a1, b1.w, acc[1][7]);
    }

    // epilogue: base + c - acc, relu, store, colsum
    const int d0 = cg * 8;
    float colp[8];
#pragma unroll
    for (int j = 0; j < 8; j++) colp[j] = 0.f;

#pragma unroll
    for (int r = 0; r < 2; r++) {
        int row = row0 + rg * 2 + r;
        float xm = (float)s_mask[row];
        float P = g_pos[row], Qn = g_neg[row];
        float v[8];
#pragma unroll
        for (int j = 0; j < 8; j++) {
            int dd = d0 + j;
            float basev = xm * svec[dd] + P * svec[D + dd] + Qn * svec[2 * D + dd];
            float un = fmaxf(basev + sC[dd] - acc[r][j], 0.f);
            v[j] = un;
            colp[j] += un;
        }
        float4* dst = (float4*)(u_out + (size_t)row * D + d0);
        dst[0] = make_float4(v[0], v[1], v[2], v[3]);
        dst[1] = make_float4(v[4], v[5], v[6], v[7]);
    }
#pragma unroll
    for (int j = 0; j < 8; j++) atomicAdd(&scol[d0 + j], colp[j]);
    __syncthreads();
    if (tid < D) atomicAdd(&g_sums[os][tid * SPAD], scol[tid]);
}

// ---------------------------------------------------------------------------
// k_final: out = relu(cat(W6 @ s_final, W7 @ u[v])) . w5   (1 block, 128 thr)
// ---------------------------------------------------------------------------
__global__ void k_final(int ib, int isum,
                        const int* __restrict__ v_ptr,
                        const float* __restrict__ W6,
                        const float* __restrict__ W7,
                        const float* __restrict__ w5,
                        float* __restrict__ out) {
    __shared__ float part[128];
    int t = threadIdx.x;
    int v = v_ptr[0];
    const float* u_fin = g_u[ib];
    float h;
    if (t < D) {
        float acc = 0.f;
#pragma unroll
        for (int k = 0; k < D; k++)
            acc = fmaf(W6[t * D + k], g_sums[isum][k * SPAD], acc);
        h = fmaxf(acc, 0.f) * w5[t];
    } else {
        int d = t - D;
        float acc = 0.f;
#pragma unroll
        for (int k = 0; k < D; k++)
            acc = fmaf(W7[d * D + k], u_fin[(size_t)v * D + k], acc);
        h = fmaxf(acc, 0.f) * w5[t];
    }
    part[t] = h;
    __syncthreads();
#pragma unroll
    for (int s = 64; s > 0; s >>= 1) {
        if (t < s) part[t] += part[t + s];
        __syncthreads();
    }
    if (t == 0) out[0] = part[0];
}

// ---------------------------------------------------------------------------
extern "C" void kernel_launch(void* const* d_in, const int* in_sizes, int n_in,
                              void* d_out, int out_size) {
    const float* graph  = (const float*)d_in[0];
    const int*   s_mask = (const int*)  d_in[1];
    const int*   v      = (const int*)  d_in[2];
    const float* w1     = (const float*)d_in[3];
    const float* W2     = (const float*)d_in[4];
    const float* W3     = (const float*)d_in[5];
    const float* w4     = (const float*)d_in[6];
    const float* w5     = (const float*)d_in[7];
    const float* W6     = (const float*)d_in[8];
    const float* W7     = (const float*)d_in[9];
    float* out = (float*)d_out;

    k_pre<<<1, 256>>>(W3, w4);
    k_rowsum<<<NN, 256>>>(graph);

    // u1 = relu(base) -> buf0, colsum -> sums[0]
    k_first<<<NN / TILE_ROWS, 256>>>(s_mask, w1);
    // u2: buf0 -> buf1, uses s1, writes s2
    k_iter2<<<NN / TILE_ROWS, 256>>>(0, 1, 0, 1, s_mask, w1, W2);
    // u3: buf1 -> buf0, uses s2, writes s3
    k_iter2<<<NN / TILE_ROWS, 256>>>(1, 0, 1, 2, s_mask, w1, W2);
    // u4: buf0 -> buf1, uses s3, writes s4
    k_iter2<<<NN / TILE_ROWS, 256>>>(0, 1, 2, 3, s_mask, w1, W2);

    k_final<<<1, 128>>>(1, 3, v, W6, W7, w5, out);
}

// round 3
// speedup vs baseline: 1.0898x; 1.0898x over previous
#include <cuda_runtime.h>

#define NN 16384
#define D 64
#define SPAD 32          // pad column-sum accumulators across L2 slices
#define NB 128           // blocks in fused kernel (<=148 SMs -> all resident)
#define RPB 128          // rows per block
#define USTRIDE 65       // sU row stride: bank-conflict-free a-loads

// Scratch (allocation-free rule: __device__ globals)
__device__ float g_pos[NN];
__device__ float g_neg[NN];
__device__ float g_ab[2 * D];             // a = W3*relu(w4), b = W3*relu(-w4)
__device__ float g_sums[4][D * SPAD];     // s1..s4 column sums (padded)
__device__ unsigned g_count;              // grid barrier arrive counter
__device__ unsigned g_gen;                // grid barrier generation

// ---------------------------------------------------------------------------
// k_pre: reset barrier state + zero atomic accumulators (inside the graph,
// every replay) and precompute a,b. 1 block x 256 threads.
// ---------------------------------------------------------------------------
__global__ void k_pre(const float* __restrict__ W3, const float* __restrict__ w4) {
    int t = threadIdx.x;
    float* s = (float*)g_sums;
    for (int i = t; i < 4 * D * SPAD; i += blockDim.x) s[i] = 0.f;
    if (t == 0) { g_count = 0u; g_gen = 0u; }
    if (t < D) {
        float a = 0.f, b = 0.f;
#pragma unroll
        for (int k = 0; k < D; k++) {
            float w = w4[k];
            float W = W3[t * D + k];
            a = fmaf(W, fmaxf(w, 0.f), a);
            b = fmaf(W, fmaxf(-w, 0.f), b);
        }
        g_ab[t]     = a;
        g_ab[D + t] = b;
    }
}

// ---------------------------------------------------------------------------
// k_rowsum: pos[i] = sum_j relu(g[i][j]), neg[i] = sum_j relu(-g[i][j]).
// One block per row, float4 streaming loads. The 1.07 GB single pass.
// ---------------------------------------------------------------------------
__global__ void k_rowsum(const float* __restrict__ graph) {
    int row = blockIdx.x;
    const float4* g = reinterpret_cast<const float4*>(graph + (size_t)row * NN);
    float p = 0.f, n = 0.f;
#pragma unroll 4
    for (int i = threadIdx.x; i < NN / 4; i += 256) {
        float4 v = __ldcs(g + i);
        p += fmaxf(v.x, 0.f) + fmaxf(v.y, 0.f) + fmaxf(v.z, 0.f) + fmaxf(v.w, 0.f);
        n += fmaxf(-v.x, 0.f) + fmaxf(-v.y, 0.f) + fmaxf(-v.z, 0.f) + fmaxf(-v.w, 0.f);
    }
#pragma unroll
    for (int o = 16; o; o >>= 1) {
        p += __shfl_xor_sync(0xffffffffu, p, o);
        n += __shfl_xor_sync(0xffffffffu, n, o);
    }
    __shared__ float sp[8], sn[8];
    int lane = threadIdx.x & 31, w = threadIdx.x >> 5;
    if (lane == 0) { sp[w] = p; sn[w] = n; }
    __syncthreads();
    if (threadIdx.x == 0) {
        float P = 0.f, Q = 0.f;
#pragma unroll
        for (int i = 0; i < 8; i++) { P += sp[i]; Q += sn[i]; }
        g_pos[row] = P;
        g_neg[row] = Q;
    }
}

// ---------------------------------------------------------------------------
// software grid barrier (all NB blocks resident by construction)
// ---------------------------------------------------------------------------
__device__ __forceinline__ void grid_bar(unsigned target) {
    __syncthreads();
    if (threadIdx.x == 0) {
        __threadfence();
        unsigned old = atomicAdd(&g_count, 1u);
        if (old == NB - 1u) {
            atomicExch(&g_count, 0u);
            __threadfence();
            atomicExch(&g_gen, target);
        } else {
            volatile unsigned* vg = &g_gen;
            while (*vg < target) { __nanosleep(64); }
            __threadfence();
        }
    }
    __syncthreads();
}

// ---------------------------------------------------------------------------
// k_mp: fused message passing (4 iterations) + readout, u resident in smem.
// 128 blocks x 256 threads, 128 rows/block, thread tile 2 rows x 8 cols
// (2 halves of 64 rows). Each smem u-row is read AND written only by lanes of
// a single warp -> in-place update is warp-ordered, no extra syncs.
// ---------------------------------------------------------------------------
__global__ __launch_bounds__(256) void k_mp(const int* __restrict__ s_mask,
                                            const int* __restrict__ v_ptr,
                                            const float* __restrict__ w1,
                                            const float* __restrict__ W2,
                                            const float* __restrict__ W6,
                                            const float* __restrict__ W7,
                                            const float* __restrict__ w5,
                                            float* __restrict__ out) {
    extern __shared__ float smem[];
    float* sU   = smem;                       // RPB * USTRIDE
    float* sW   = sU + RPB * USTRIDE;         // D*D : W2^T  sW[k*64+d]
    float* svec = sW + D * D;                 // 3*D : w1 | a | b
    float* sC   = svec + 3 * D;               // D   : c = W2 @ s
    float* scol = sC + D;                     // D   : block column sums
    float* sP   = scol + D;                   // RPB
    float* sNg  = sP + RPB;                   // RPB
    float* sX   = sNg + RPB;                  // RPB
    float* part = sX + RPB;                   // 128 : final reduction

    const int tid  = threadIdx.x;
    const int row0 = blockIdx.x * RPB;

    // ---- prologue ----
#pragma unroll
    for (int t = 0; t < 16; t++) {            // W2[d][k] -> sW[k*64+d]
        int p = tid + t * 256;
        sW[(p & 63) * D + (p >> 6)] = W2[p];
    }
    if (tid < D) {
        svec[tid]         = w1[tid];
        svec[D + tid]     = g_ab[tid];
        svec[2 * D + tid] = g_ab[D + tid];
        scol[tid] = 0.f;
    }
    if (tid < RPB) {
        sP[tid]  = g_pos[row0 + tid];
        sNg[tid] = g_neg[row0 + tid];
        sX[tid]  = (float)s_mask[row0 + tid];
    }
    __syncthreads();

    const int cg = tid & 7;                   // col group: cols cg*8..+7
    const int rg = tid >> 3;                  // row group: 0..31
    const int d0 = cg * 8;

    // ---- iteration 1: u1 = relu(base) ----
    {
        float colp[8];
#pragma unroll
        for (int j = 0; j < 8; j++) colp[j] = 0.f;
#pragma unroll
        for (int half = 0; half < 2; half++) {
#pragma unroll
            for (int r = 0; r < 2; r++) {
                int lr = half * 64 + rg * 2 + r;
                float xm = sX[lr], P = sP[lr], Ng = sNg[lr];
#pragma unroll
                for (int j = 0; j < 8; j++) {
                    int dd = d0 + j;
                    float un = fmaxf(xm * svec[dd] + P * svec[D + dd] + Ng * svec[2 * D + dd], 0.f);
                    sU[lr * USTRIDE + dd] = un;
                    colp[j] += un;
                }
            }
        }
#pragma unroll
        for (int j = 0; j < 8; j++) atomicAdd(&scol[d0 + j], colp[j]);
        __syncthreads();
        if (tid < D) atomicAdd(&g_sums[0][tid * SPAD], scol[tid]);
        grid_bar(1);
    }

    // ---- iterations 2..4 ----
    for (int it = 1; it < 4; it++) {
        if (tid < D) {
            float acc = 0.f;
#pragma unroll
            for (int k = 0; k < D; k++)
                acc = fmaf(sW[k * D + tid], __ldcg(&g_sums[it - 1][k * SPAD]), acc);
            sC[tid] = acc;
            scol[tid] = 0.f;
        }
        __syncthreads();

        float colp[8];
#pragma unroll
        for (int j = 0; j < 8; j++) colp[j] = 0.f;

#pragma unroll
        for (int half = 0; half < 2; half++) {
            float acc[2][8];
#pragma unroll
            for (int r = 0; r < 2; r++)
#pragma unroll
                for (int j = 0; j < 8; j++) acc[r][j] = 0.f;

            const float* uB = &sU[(half * 64 + rg * 2) * USTRIDE];
            const float* wB = &sW[d0];
#pragma unroll 8
            for (int k = 0; k < D; k++) {
                float4 b0 = *(const float4*)(wB + k * D);
                float4 b1 = *(const float4*)(wB + k * D + 4);
                float a0 = uB[k];
                float a1 = uB[USTRIDE + k];
                acc[0][0] = fmaf(a0, b0.x, acc[0][0]);
                acc[0][1] = fmaf(a0, b0.y, acc[0][1]);
                acc[0][2] = fmaf(a0, b0.z, acc[0][2]);
                acc[0][3] = fmaf(a0, b0.w, acc[0][3]);
                acc[0][4] = fmaf(a0, b1.x, acc[0][4]);
                acc[0][5] = fmaf(a0, b1.y, acc[0][5]);
                acc[0][6] = fmaf(a0, b1.z, acc[0][6]);
                acc[0][7] = fmaf(a0, b1.w, acc[0][7]);
                acc[1][0] = fmaf(a1, b0.x, acc[1][0]);
                acc[1][1] = fmaf(a1, b0.y, acc[1][1]);
                acc[1][2] = fmaf(a1, b0.z, acc[1][2]);
                acc[1][3] = fmaf(a1, b0.w, acc[1][3]);
                acc[1][4] = fmaf(a1, b1.x, acc[1][4]);
                acc[1][5] = fmaf(a1, b1.y, acc[1][5]);
                acc[1][6] = fmaf(a1, b1.z, acc[1][6]);
                acc[1][7] = fmaf(a1, b1.w, acc[1][7]);
            }
            // in-place epilogue (rows owned by this warp only)
#pragma unroll
            for (int r = 0; r < 2; r++) {
                int lr = half * 64 + rg * 2 + r;
                float xm = sX[lr], P = sP[lr], Ng = sNg[lr];
#pragma unroll
                for (int j = 0; j < 8; j++) {
                    int dd = d0 + j;
                    float basev = xm * svec[dd] + P * svec[D + dd] + Ng * svec[2 * D + dd];
                    float un = fmaxf(basev + sC[dd] - acc[r][j], 0.f);
                    sU[lr * USTRIDE + dd] = un;
                    colp[j] += un;
                }
            }
        }
#pragma unroll
        for (int j = 0; j < 8; j++) atomicAdd(&scol[d0 + j], colp[j]);
        __syncthreads();
        if (tid < D) atomicAdd(&g_sums[it][tid * SPAD], scol[tid]);
        grid_bar((unsigned)(it + 1));
    }

    // ---- readout: only the block owning row v ----
    int v = v_ptr[0];
    if (blockIdx.x == (unsigned)(v / RPB)) {
        if (tid < 2 * D) {
            float h;
            if (tid < D) {
                float acc = 0.f;
#pragma unroll
                for (int k = 0; k < D; k++)
                    acc = fmaf(W6[tid * D + k], __ldcg(&g_sums[3][k * SPAD]), acc);
                h = fmaxf(acc, 0.f) * w5[tid];
            } else {
                int d = tid - D;
                int lv = v - blockIdx.x * RPB;
                float acc = 0.f;
#pragma unroll
                for (int k = 0; k < D; k++)
                    acc = fmaf(W7[d * D + k], sU[lv * USTRIDE + k], acc);
                h = fmaxf(acc, 0.f) * w5[tid];
            }
            part[tid] = h;
        }
        __syncthreads();
        if (tid == 0) {
            float s = 0.f;
#pragma unroll
            for (int i = 0; i < 2 * D; i++) s += part[i];
            out[0] = s;
        }
    }
}

// ---------------------------------------------------------------------------
extern "C" void kernel_launch(void* const* d_in, const int* in_sizes, int n_in,
                              void* d_out, int out_size) {
    const float* graph  = (const float*)d_in[0];
    const int*   s_mask = (const int*)  d_in[1];
    const int*   v      = (const int*)  d_in[2];
    const float* w1     = (const float*)d_in[3];
    const float* W2     = (const float*)d_in[4];
    const float* W3     = (const float*)d_in[5];
    const float* w4     = (const float*)d_in[6];
    const float* w5     = (const float*)d_in[7];
    const float* W6     = (const float*)d_in[8];
    const float* W7     = (const float*)d_in[9];
    float* out = (float*)d_out;

    // dynamic smem: sU + sW + svec + sC + scol + sP + sNg + sX + part
    const int smem_floats = RPB * USTRIDE + D * D + 3 * D + D + D + 3 * RPB + 128;
    const int smem_bytes  = smem_floats * 4;
    cudaFuncSetAttribute(k_mp, cudaFuncAttributeMaxDynamicSharedMemorySize, smem_bytes);

    k_pre<<<1, 256>>>(W3, w4);
    k_rowsum<<<NN, 256>>>(graph);
    k_mp<<<NB, 256, smem_bytes>>>(s_mask, v, w1, W2, W6, W7, w5, out);
}